// round 8
// baseline (speedup 1.0000x reference)
#include <cuda_runtime.h>
#include <math.h>

// Problem shape (fixed by the dataset)
#define Bn 16
#define Qn 300
#define Tn 50
#define Cn 80          // NUM_CLASSES
#define Hn 128
#define Wn 128
#define NJ (Bn*Tn)                 // 800
#define HM_ELEMS (Bn*Cn*Hn*Wn)     // 20,971,520
#define HM4 (HM_ELEMS/4)           // 5,242,880 float4
#define HASHN 2048
#define G  296                     // grid (2 blocks/SM on 148 SMs)
#define BT 512                     // block size
#define NW (BT/32)                 // 16 warps
#define CH 512                     // float4 per chunk unit
// static quotas (chunks): prep=4, CE=30, normal=36 -> 4 + 64*30 + 231*36 = 10240 = HM4/CH
#define Q_PREP 4
#define Q_CE   30
#define Q_NORM 36

// Per-block partial slots (overwritten every launch -> no zeroing needed)
__device__ double p_hm[G], p_cn[G], p_cd[G];
__device__ double p_box, p_bb, p_gi;
__device__ int    p_np;
__device__ unsigned g_arrive = 0;   // self-wrapping arrival counter

struct PrepSh {
    float bfs[NJ][4];
    int   key3s[NJ];
    int   hashA[HASHN];   // dedupe (b,label,gy,gx)
    int   hashBk[HASHN];  // keys   (b,gy,gx)
    int   hashBv[HASHN];  // last-wins winner j per key
    int   snum;
};
struct CeSh { int tc[Qn]; };
union ShU { PrepSh prep; CeSh ce; };

// focal loss at target==0: 0.75 * sigmoid(x)^2 * softplus(x)
// 3-MUFU version using ONLY known-rt8 MUFU ops (EX2, RCP, LG2); 9 instrs/elem.
//   u = e^x ; r = 1/(1+u) ; p = u*r = sigmoid(x)
//   softplus(x) = -ln(r)  =>  loss = 0.75*p^2*(-ln2*log2(r))
__device__ __forceinline__ float floss0(float x) {
    float u, r, lg;
    asm("ex2.approx.f32 %0, %1;" : "=f"(u) : "f"(x * 1.4426950409f));
    asm("rcp.approx.f32 %0, %1;" : "=f"(r) : "f"(1.f + u));
    const float p = u * r;
    asm("lg2.approx.f32 %0, %1;" : "=f"(lg) : "f"(r));
    return -0.51986038f * (p * p) * lg;
}

__global__ void __launch_bounds__(BT, 2)
k_all(const float*  __restrict__ pred_logits,
      const float*  __restrict__ pred_boxes,
      const float4* __restrict__ hm4,
      const float*  __restrict__ hm,
      const float*  __restrict__ box_map,
      const float*  __restrict__ tgt_boxes,
      const int*    __restrict__ tgt_labels,
      const float*  __restrict__ tgt_sizes,
      const int*    __restrict__ src_idx,
      const int*    __restrict__ tgt_idx,
      const float*  __restrict__ empty_weight,
      float* __restrict__ out)
{
    __shared__ ShU    sh;
    __shared__ float  redf[NW][6];
    __shared__ double redd[NW][3];
    __shared__ bool   isLast;

    const int tid  = threadIdx.x;
    const int bid  = blockIdx.x;
    const int lane = tid & 31, wrp = tid >> 5;

    float corr = 0.f, myBox = 0.f, myBb = 0.f, myGi = 0.f;
    float ceN = 0.f, ceD = 0.f;

    // ======================= block 0: prep =======================
    if (bid == 0) {
        for (int i = tid; i < HASHN; i += BT) {
            sh.prep.hashA[i] = -1; sh.prep.hashBk[i] = -1; sh.prep.hashBv[i] = -1;
        }
        if (tid == 0) sh.prep.snum = 0;
        __syncthreads();

        // phase 1: normalized boxes + hash inserts + focal corrections (exact math)
        for (int j = tid; j < NJ; j += BT) {
            const int b = j / Tn;
            const float h_im = tgt_sizes[b*2 + 0];
            const float w_im = tgt_sizes[b*2 + 1];
            const float4 tb = ((const float4*)tgt_boxes)[j];
            const float x1 = tb.x / w_im, y1 = tb.y / h_im;
            const float x2 = tb.z / w_im, y2 = tb.w / h_im;
            const float cx = 0.5f*(x1 + x2), cy = 0.5f*(y1 + y2);
            sh.prep.bfs[j][0] = cx;      sh.prep.bfs[j][1] = cy;
            sh.prep.bfs[j][2] = x2 - x1; sh.prep.bfs[j][3] = y2 - y1;

            const int lf = tgt_labels[j];
            const int gx = min(max((int)(cx * (float)Wn), 0), Wn - 1);
            const int gy = min(max((int)(cy * (float)Hn), 0), Hn - 1);
            const int key3 = (b*Hn + gy)*Wn + gx;
            sh.prep.key3s[j] = key3;
            const int key4 = ((b*Cn + lf)*Hn + gy)*Wn + gx;

            unsigned hh = ((unsigned)key4 * 2654435761u) & (HASHN - 1);
            bool ins = false;
            for (;;) {
                int prev = atomicCAS(&sh.prep.hashA[hh], -1, key4);
                if (prev == -1) { ins = true; break; }
                if (prev == key4) break;
                hh = (hh + 1) & (HASHN - 1);
            }
            if (ins) {
                const float x   = hm[key4];
                const float ax  = fabsf(x);
                const float l1p = log1pf(expf(-ax));
                const float ce1 = fmaxf(x, 0.f) - x + l1p;   // target = 1
                const float ce0 = fmaxf(x, 0.f) + l1p;       // target = 0
                const float pr  = 1.f / (1.f + expf(-x));
                const float l1  = 0.25f * (1.f - pr) * (1.f - pr) * ce1;
                const float l0  = 0.75f * pr * pr * ce0;
                corr += l1 - l0;
            }

            hh = ((unsigned)key3 * 2654435761u) & (HASHN - 1);
            int slot;
            for (;;) {
                int prev = atomicCAS(&sh.prep.hashBk[hh], -1, key3);
                if (prev == -1) { atomicAdd(&sh.prep.snum, 1); slot = hh; break; }
                if (prev == key3) { slot = hh; break; }
                hh = (hh + 1) & (HASHN - 1);
            }
            atomicMax(&sh.prep.hashBv[slot], j);
        }
        __syncthreads();

        // phase 2: box_map correction (winners only) + pair L1 + GIoU
        for (int j = tid; j < NJ; j += BT) {
            const int b    = j / Tn;
            const int key3 = sh.prep.key3s[j];
            const int gx   = key3 & (Wn - 1);
            const int gy   = (key3 >> 7) & (Hn - 1);

            unsigned hh = ((unsigned)key3 * 2654435761u) & (HASHN - 1);
            while (sh.prep.hashBk[hh] != key3) hh = (hh + 1) & (HASHN - 1);
            if (sh.prep.hashBv[hh] == j) {
                #pragma unroll
                for (int c = 0; c < 4; c++) {
                    const float bm = box_map[((b*4 + c)*Hn + gy)*Wn + gx];
                    myBox += fabsf(bm - sh.prep.bfs[j][c]);
                }
            }

            const int si = src_idx[j];
            const int ti = tgt_idx[j];
            const float4 sb = ((const float4*)pred_boxes)[b*Qn + si];
            const float s0 = sb.x, s1 = sb.y, s2 = sb.z, s3 = sb.w;
            const float* mb = sh.prep.bfs[b*Tn + ti];
            const float m0 = mb[0], m1 = mb[1], m2 = mb[2], m3 = mb[3];

            myBb += fabsf(s0-m0) + fabsf(s1-m1) + fabsf(s2-m2) + fabsf(s3-m3);

            const float ax1 = s0 - 0.5f*s2, ay1 = s1 - 0.5f*s3;
            const float ax2 = s0 + 0.5f*s2, ay2 = s1 + 0.5f*s3;
            const float bx1 = m0 - 0.5f*m2, by1 = m1 - 0.5f*m3;
            const float bx2 = m0 + 0.5f*m2, by2 = m1 + 0.5f*m3;
            const float area_a = (ax2-ax1)*(ay2-ay1);
            const float area_b = (bx2-bx1)*(by2-by1);
            const float iw = fmaxf(fminf(ax2,bx2) - fmaxf(ax1,bx1), 0.f);
            const float ih = fmaxf(fminf(ay2,by2) - fmaxf(ay1,by1), 0.f);
            const float inter = iw*ih;
            const float uni   = area_a + area_b - inter;
            const float iou   = inter / uni;
            const float cw_   = fmaxf(fmaxf(ax2,bx2) - fminf(ax1,bx1), 0.f);
            const float ch_   = fmaxf(fmaxf(ay2,by2) - fminf(ay1,by1), 0.f);
            const float ac    = cw_ * ch_;
            myGi += 1.f - (iou - (ac - uni)/ac);
        }
        if (tid == 0) p_np = sh.prep.snum;
    }
    // ======================= blocks 1..64: weighted CE =======================
    else if (bid <= 64) {
        const int idx = bid - 1;
        const int b   = idx >> 2;
        const int seg = idx & 3;
        for (int i = tid; i < Qn; i += BT) sh.ce.tc[i] = Cn;
        __syncthreads();
        if (tid < Tn) {
            const int s = src_idx[b*Tn + tid];
            sh.ce.tc[s] = tgt_labels[b*Tn + tgt_idx[b*Tn + tid]];
        }
        __syncthreads();
        for (int q = seg*75 + wrp; q < seg*75 + 75; q += NW) {
            const float* row = pred_logits + (size_t)(b*Qn + q) * (Cn + 1);
            const float x0 = row[lane];
            const float x1 = row[lane + 32];
            const float x2 = (lane < 17) ? row[lane + 64] : -3.4e38f;
            float mx = fmaxf(fmaxf(x0, x1), x2);
            #pragma unroll
            for (int o = 16; o; o >>= 1) mx = fmaxf(mx, __shfl_xor_sync(0xffffffffu, mx, o));
            float se = __expf(x0 - mx) + __expf(x1 - mx) + ((lane < 17) ? __expf(x2 - mx) : 0.f);
            #pragma unroll
            for (int o = 16; o; o >>= 1) se += __shfl_xor_sync(0xffffffffu, se, o);
            if (lane == 0) {
                const int t = sh.ce.tc[q];
                ceN += empty_weight[t] * (mx + __logf(se) - row[t]);
                ceD += empty_weight[t];
            }
        }
    }

    // ===== all blocks: focal base stream, STATIC contiguous region, no sync =====
    // Region (in CH=512-float4 chunk units), load-compensated:
    //   bid 0      : [0, 4)
    //   bid 1..64  : [4 + (bid-1)*30, +30)
    //   bid 65..   : [1924 + (bid-65)*36, +36)
    float fs = 0.f;
    {
        int cs, cq;
        if (bid == 0)       { cs = 0;                      cq = Q_PREP; }
        else if (bid <= 64) { cs = Q_PREP + (bid-1)*Q_CE;  cq = Q_CE;   }
        else                { cs = Q_PREP + 64*Q_CE + (bid-65)*Q_NORM; cq = Q_NORM; }
        const int rs = cs * CH;          // region start (float4)
        const int re = rs + cq * CH;     // region end

        int i = rs + tid;
        for (; i + 7*BT < re; i += 8*BT) {
            float4 r[8];
            #pragma unroll
            for (int k = 0; k < 8; k++) r[k] = __ldcs(&hm4[i + k*BT]);
            #pragma unroll
            for (int k = 0; k < 8; k++)
                fs += floss0(r[k].x) + floss0(r[k].y) + floss0(r[k].z) + floss0(r[k].w);
        }
        for (; i < re; i += BT) {
            const float4 a = __ldcs(&hm4[i]);
            fs += floss0(a.x) + floss0(a.y) + floss0(a.z) + floss0(a.w);
        }
    }
    fs += corr;   // block 0 folds its focal corrections into its partial

    // ======================= block reduction of 6 partials =======================
    float v0 = fs, v1 = ceN, v2 = ceD, v3 = myBox, v4 = myBb, v5 = myGi;
    #pragma unroll
    for (int o = 16; o; o >>= 1) {
        v0 += __shfl_xor_sync(0xffffffffu, v0, o);
        v1 += __shfl_xor_sync(0xffffffffu, v1, o);
        v2 += __shfl_xor_sync(0xffffffffu, v2, o);
        v3 += __shfl_xor_sync(0xffffffffu, v3, o);
        v4 += __shfl_xor_sync(0xffffffffu, v4, o);
        v5 += __shfl_xor_sync(0xffffffffu, v5, o);
    }
    if (lane == 0) {
        redf[wrp][0]=v0; redf[wrp][1]=v1; redf[wrp][2]=v2;
        redf[wrp][3]=v3; redf[wrp][4]=v4; redf[wrp][5]=v5;
    }
    __syncthreads();
    if (wrp == 0) {
        v0 = (lane < NW) ? redf[lane][0] : 0.f;
        v1 = (lane < NW) ? redf[lane][1] : 0.f;
        v2 = (lane < NW) ? redf[lane][2] : 0.f;
        v3 = (lane < NW) ? redf[lane][3] : 0.f;
        v4 = (lane < NW) ? redf[lane][4] : 0.f;
        v5 = (lane < NW) ? redf[lane][5] : 0.f;
        #pragma unroll
        for (int o = 16; o; o >>= 1) {
            v0 += __shfl_xor_sync(0xffffffffu, v0, o);
            v1 += __shfl_xor_sync(0xffffffffu, v1, o);
            v2 += __shfl_xor_sync(0xffffffffu, v2, o);
            v3 += __shfl_xor_sync(0xffffffffu, v3, o);
            v4 += __shfl_xor_sync(0xffffffffu, v4, o);
            v5 += __shfl_xor_sync(0xffffffffu, v5, o);
        }
        if (lane == 0) {
            p_hm[bid] = (double)v0;
            p_cn[bid] = (double)v1;
            p_cd[bid] = (double)v2;
            if (bid == 0) { p_box = (double)v3; p_bb = (double)v4; p_gi = (double)v5; }
        }
    }

    // ======================= last-block finalize =======================
    __threadfence();
    if (tid == 0) isLast = (atomicInc(&g_arrive, G - 1) == G - 1);  // wraps to 0
    __syncthreads();
    if (isLast) {
        __threadfence();
        double a = 0.0, b2 = 0.0, c2 = 0.0;
        for (int i = tid; i < G; i += BT) {
            a  += ((volatile double*)p_hm)[i];
            b2 += ((volatile double*)p_cn)[i];
            c2 += ((volatile double*)p_cd)[i];
        }
        #pragma unroll
        for (int o = 16; o; o >>= 1) {
            a  += __shfl_xor_sync(0xffffffffu, a,  o);
            b2 += __shfl_xor_sync(0xffffffffu, b2, o);
            c2 += __shfl_xor_sync(0xffffffffu, c2, o);
        }
        if (lane == 0) { redd[wrp][0] = a; redd[wrp][1] = b2; redd[wrp][2] = c2; }
        __syncthreads();
        if (wrp == 0) {
            a  = (lane < NW) ? redd[lane][0] : 0.0;
            b2 = (lane < NW) ? redd[lane][1] : 0.0;
            c2 = (lane < NW) ? redd[lane][2] : 0.0;
            #pragma unroll
            for (int o = 16; o; o >>= 1) {
                a  += __shfl_xor_sync(0xffffffffu, a,  o);
                b2 += __shfl_xor_sync(0xffffffffu, b2, o);
                c2 += __shfl_xor_sync(0xffffffffu, c2, o);
            }
            if (lane == 0) {
                const double boxc = *((volatile double*)&p_box);
                const double bb   = *((volatile double*)&p_bb);
                const double gi   = *((volatile double*)&p_gi);
                const int    npI  = *((volatile int*)&p_np);
                const double np   = fmax((double)npI, 1.0);
                const float ce   = (float)(b2 / c2);
                const float bbox = (float)(bb / (double)NJ);
                const float giou = (float)(gi / (double)NJ);
                const float hmv  = (float)(a / np);
                const float bl   = (float)(boxc / np);
                const float aux  = hmv + 5.f * bl;
                out[0] = ce;
                out[1] = bbox;
                out[2] = giou;
                out[3] = aux;
                out[4] = ce + 5.f * bbox + 2.f * giou + aux;
            }
        }
    }
}

extern "C" void kernel_launch(void* const* d_in, const int* in_sizes, int n_in,
                              void* d_out, int out_size)
{
    const float* pred_logits  = (const float*)d_in[0];
    const float* pred_boxes   = (const float*)d_in[1];
    const float* heatmap      = (const float*)d_in[2];
    const float* box_map      = (const float*)d_in[3];
    const float* tgt_boxes    = (const float*)d_in[4];
    const int*   tgt_labels   = (const int*)  d_in[5];
    const float* tgt_sizes    = (const float*)d_in[6];
    const int*   src_idx      = (const int*)  d_in[7];
    const int*   tgt_idx      = (const int*)  d_in[8];
    const float* empty_weight = (const float*)d_in[9];

    k_all<<<G, BT>>>(pred_logits, pred_boxes,
                     (const float4*)heatmap, heatmap, box_map, tgt_boxes,
                     tgt_labels, tgt_sizes, src_idx, tgt_idx, empty_weight,
                     (float*)d_out);
}

// round 9
// speedup vs baseline: 1.2796x; 1.2796x over previous
#include <cuda_runtime.h>
#include <math.h>

// Problem shape (fixed by the dataset)
#define Bn 16
#define Qn 300
#define Tn 50
#define Cn 80          // NUM_CLASSES
#define Hn 128
#define Wn 128
#define NJ (Bn*Tn)                 // 800
#define HM_ELEMS (Bn*Cn*Hn*Wn)     // 20,971,520
#define HM4 (HM_ELEMS/4)           // 5,242,880 float4
#define HASHN 2048
#define G  296                     // grid (2 blocks/SM on 148 SMs)
#define BT 512                     // block size
#define NW (BT/32)                 // 16 warps
#define CH 512                     // float4 per chunk unit
// static quotas (chunks): prep=4, CE=30, normal=36 -> 4 + 64*30 + 231*36 = 10240 = HM4/CH
#define Q_PREP 4
#define Q_CE   30
#define Q_NORM 36

// Per-block partial slots (overwritten every launch -> no zeroing needed)
__device__ double p_hm[G], p_cn[G], p_cd[G];
__device__ double p_box, p_bb, p_gi;
__device__ int    p_np;
__device__ unsigned g_arrive = 0;   // self-wrapping arrival counter

struct PrepSh {
    float bfs[NJ][4];
    int   key3s[NJ];
    int   hashA[HASHN];   // dedupe (b,label,gy,gx)
    int   hashBk[HASHN];  // keys   (b,gy,gx)
    int   hashBv[HASHN];  // last-wins winner j per key
    int   snum;
};
struct CeSh { int tc[Qn]; };
union ShU { PrepSh prep; CeSh ce; };

typedef unsigned long long ull;

__device__ __forceinline__ ull pack2(float lo, float hi) {
    ull r; asm("mov.b64 %0, {%1, %2};" : "=l"(r) : "f"(lo), "f"(hi)); return r;
}
__device__ __forceinline__ void unpack2(ull v, float &lo, float &hi) {
    asm("mov.b64 {%0, %1}, %2;" : "=f"(lo), "=f"(hi) : "l"(v));
}

// focal loss at target==0 over a PAIR of elements, f32x2-packed FP ops.
// Identical math to scalar R6: th=tanh(x/2); q=0.5-0.5th; m=1+th;
// loss = -0.12996509 * m^2 * lg2(q)   [= 0.75*sigmoid^2*softplus]
__device__ __forceinline__ void floss0_pair(float x0, float x1,
                                            ull half2, ull nhalf2, ull one2, ull negc2,
                                            ull &acc) {
    ull xp = pack2(x0, x1), tp, thp, qp, lgp, mp, mmp, zp;
    asm("mul.rn.f32x2 %0, %1, %2;" : "=l"(tp) : "l"(xp), "l"(half2));
    float t0, t1, th0, th1, q0, q1, lg0, lg1;
    unpack2(tp, t0, t1);
    asm("tanh.approx.f32 %0, %1;" : "=f"(th0) : "f"(t0));
    asm("tanh.approx.f32 %0, %1;" : "=f"(th1) : "f"(t1));
    thp = pack2(th0, th1);
    asm("fma.rn.f32x2 %0, %1, %2, %3;" : "=l"(qp) : "l"(thp), "l"(nhalf2), "l"(half2));
    unpack2(qp, q0, q1);
    asm("lg2.approx.f32 %0, %1;" : "=f"(lg0) : "f"(q0));
    asm("lg2.approx.f32 %0, %1;" : "=f"(lg1) : "f"(q1));
    lgp = pack2(lg0, lg1);
    asm("add.rn.f32x2 %0, %1, %2;" : "=l"(mp) : "l"(thp), "l"(one2));
    asm("mul.rn.f32x2 %0, %1, %2;" : "=l"(mmp) : "l"(mp), "l"(mp));
    asm("mul.rn.f32x2 %0, %1, %2;" : "=l"(zp) : "l"(mmp), "l"(lgp));
    asm("fma.rn.f32x2 %0, %1, %2, %3;" : "=l"(acc) : "l"(zp), "l"(negc2), "l"(acc));
}

// scalar version (prep corrections only)
__device__ __forceinline__ float floss0s(float x) {
    float th;
    asm("tanh.approx.f32 %0, %1;" : "=f"(th) : "f"(0.5f * x));
    const float q = 0.5f - 0.5f * th;
    const float m = 1.f + th;
    float lg;
    asm("lg2.approx.f32 %0, %1;" : "=f"(lg) : "f"(q));
    return -0.12996509f * (m * m) * lg;
}

__global__ void __launch_bounds__(BT, 2)
k_all(const float*  __restrict__ pred_logits,
      const float*  __restrict__ pred_boxes,
      const float4* __restrict__ hm4,
      const float*  __restrict__ hm,
      const float*  __restrict__ box_map,
      const float*  __restrict__ tgt_boxes,
      const int*    __restrict__ tgt_labels,
      const float*  __restrict__ tgt_sizes,
      const int*    __restrict__ src_idx,
      const int*    __restrict__ tgt_idx,
      const float*  __restrict__ empty_weight,
      float* __restrict__ out)
{
    __shared__ ShU    sh;
    __shared__ float  redf[NW][6];
    __shared__ double redd[NW][3];
    __shared__ bool   isLast;

    const int tid  = threadIdx.x;
    const int bid  = blockIdx.x;
    const int lane = tid & 31, wrp = tid >> 5;

    float corr = 0.f, myBox = 0.f, myBb = 0.f, myGi = 0.f;
    float ceN = 0.f, ceD = 0.f;

    // ======================= block 0: prep =======================
    if (bid == 0) {
        for (int i = tid; i < HASHN; i += BT) {
            sh.prep.hashA[i] = -1; sh.prep.hashBk[i] = -1; sh.prep.hashBv[i] = -1;
        }
        if (tid == 0) sh.prep.snum = 0;
        __syncthreads();

        // phase 1: normalized boxes + hash inserts + focal corrections (exact math)
        for (int j = tid; j < NJ; j += BT) {
            const int b = j / Tn;
            const float h_im = tgt_sizes[b*2 + 0];
            const float w_im = tgt_sizes[b*2 + 1];
            const float4 tb = ((const float4*)tgt_boxes)[j];
            const float x1 = tb.x / w_im, y1 = tb.y / h_im;
            const float x2 = tb.z / w_im, y2 = tb.w / h_im;
            const float cx = 0.5f*(x1 + x2), cy = 0.5f*(y1 + y2);
            sh.prep.bfs[j][0] = cx;      sh.prep.bfs[j][1] = cy;
            sh.prep.bfs[j][2] = x2 - x1; sh.prep.bfs[j][3] = y2 - y1;

            const int lf = tgt_labels[j];
            const int gx = min(max((int)(cx * (float)Wn), 0), Wn - 1);
            const int gy = min(max((int)(cy * (float)Hn), 0), Hn - 1);
            const int key3 = (b*Hn + gy)*Wn + gx;
            sh.prep.key3s[j] = key3;
            const int key4 = ((b*Cn + lf)*Hn + gy)*Wn + gx;

            unsigned hh = ((unsigned)key4 * 2654435761u) & (HASHN - 1);
            bool ins = false;
            for (;;) {
                int prev = atomicCAS(&sh.prep.hashA[hh], -1, key4);
                if (prev == -1) { ins = true; break; }
                if (prev == key4) break;
                hh = (hh + 1) & (HASHN - 1);
            }
            if (ins) {
                const float x   = hm[key4];
                const float ax  = fabsf(x);
                const float l1p = log1pf(expf(-ax));
                const float ce1 = fmaxf(x, 0.f) - x + l1p;   // target = 1
                const float ce0 = fmaxf(x, 0.f) + l1p;       // target = 0
                const float pr  = 1.f / (1.f + expf(-x));
                const float l1  = 0.25f * (1.f - pr) * (1.f - pr) * ce1;
                const float l0  = 0.75f * pr * pr * ce0;
                corr += l1 - l0;
            }

            hh = ((unsigned)key3 * 2654435761u) & (HASHN - 1);
            int slot;
            for (;;) {
                int prev = atomicCAS(&sh.prep.hashBk[hh], -1, key3);
                if (prev == -1) { atomicAdd(&sh.prep.snum, 1); slot = hh; break; }
                if (prev == key3) { slot = hh; break; }
                hh = (hh + 1) & (HASHN - 1);
            }
            atomicMax(&sh.prep.hashBv[slot], j);
        }
        __syncthreads();

        // phase 2: box_map correction (winners only) + pair L1 + GIoU
        for (int j = tid; j < NJ; j += BT) {
            const int b    = j / Tn;
            const int key3 = sh.prep.key3s[j];
            const int gx   = key3 & (Wn - 1);
            const int gy   = (key3 >> 7) & (Hn - 1);

            unsigned hh = ((unsigned)key3 * 2654435761u) & (HASHN - 1);
            while (sh.prep.hashBk[hh] != key3) hh = (hh + 1) & (HASHN - 1);
            if (sh.prep.hashBv[hh] == j) {
                #pragma unroll
                for (int c = 0; c < 4; c++) {
                    const float bm = box_map[((b*4 + c)*Hn + gy)*Wn + gx];
                    myBox += fabsf(bm - sh.prep.bfs[j][c]);
                }
            }

            const int si = src_idx[j];
            const int ti = tgt_idx[j];
            const float4 sb = ((const float4*)pred_boxes)[b*Qn + si];
            const float s0 = sb.x, s1 = sb.y, s2 = sb.z, s3 = sb.w;
            const float* mb = sh.prep.bfs[b*Tn + ti];
            const float m0 = mb[0], m1 = mb[1], m2 = mb[2], m3 = mb[3];

            myBb += fabsf(s0-m0) + fabsf(s1-m1) + fabsf(s2-m2) + fabsf(s3-m3);

            const float ax1 = s0 - 0.5f*s2, ay1 = s1 - 0.5f*s3;
            const float ax2 = s0 + 0.5f*s2, ay2 = s1 + 0.5f*s3;
            const float bx1 = m0 - 0.5f*m2, by1 = m1 - 0.5f*m3;
            const float bx2 = m0 + 0.5f*m2, by2 = m1 + 0.5f*m3;
            const float area_a = (ax2-ax1)*(ay2-ay1);
            const float area_b = (bx2-bx1)*(by2-by1);
            const float iw = fmaxf(fminf(ax2,bx2) - fmaxf(ax1,bx1), 0.f);
            const float ih = fmaxf(fminf(ay2,by2) - fmaxf(ay1,by1), 0.f);
            const float inter = iw*ih;
            const float uni   = area_a + area_b - inter;
            const float iou   = inter / uni;
            const float cw_   = fmaxf(fmaxf(ax2,bx2) - fminf(ax1,bx1), 0.f);
            const float ch_   = fmaxf(fmaxf(ay2,by2) - fminf(ay1,by1), 0.f);
            const float ac    = cw_ * ch_;
            myGi += 1.f - (iou - (ac - uni)/ac);
        }
        if (tid == 0) p_np = sh.prep.snum;
    }
    // ======================= blocks 1..64: weighted CE =======================
    else if (bid <= 64) {
        const int idx = bid - 1;
        const int b   = idx >> 2;
        const int seg = idx & 3;
        for (int i = tid; i < Qn; i += BT) sh.ce.tc[i] = Cn;
        __syncthreads();
        if (tid < Tn) {
            const int s = src_idx[b*Tn + tid];
            sh.ce.tc[s] = tgt_labels[b*Tn + tgt_idx[b*Tn + tid]];
        }
        __syncthreads();
        for (int q = seg*75 + wrp; q < seg*75 + 75; q += NW) {
            const float* row = pred_logits + (size_t)(b*Qn + q) * (Cn + 1);
            const float x0 = row[lane];
            const float x1 = row[lane + 32];
            const float x2 = (lane < 17) ? row[lane + 64] : -3.4e38f;
            float mx = fmaxf(fmaxf(x0, x1), x2);
            #pragma unroll
            for (int o = 16; o; o >>= 1) mx = fmaxf(mx, __shfl_xor_sync(0xffffffffu, mx, o));
            float se = __expf(x0 - mx) + __expf(x1 - mx) + ((lane < 17) ? __expf(x2 - mx) : 0.f);
            #pragma unroll
            for (int o = 16; o; o >>= 1) se += __shfl_xor_sync(0xffffffffu, se, o);
            if (lane == 0) {
                const int t = sh.ce.tc[q];
                ceN += empty_weight[t] * (mx + __logf(se) - row[t]);
                ceD += empty_weight[t];
            }
        }
    }

    // ===== all blocks: focal base stream, STATIC contiguous region, no sync =====
    // Region (in CH=512-float4 chunk units), load-compensated:
    //   bid 0      : [0, 4)
    //   bid 1..64  : [4 + (bid-1)*30, +30)
    //   bid 65..   : [1924 + (bid-65)*36, +36)
    float fs = 0.f;
    {
        int cs, cq;
        if (bid == 0)       { cs = 0;                      cq = Q_PREP; }
        else if (bid <= 64) { cs = Q_PREP + (bid-1)*Q_CE;  cq = Q_CE;   }
        else                { cs = Q_PREP + 64*Q_CE + (bid-65)*Q_NORM; cq = Q_NORM; }
        const int rs = cs * CH;          // region start (float4)
        const int re = rs + cq * CH;     // region end

        const ull half2  = pack2(0.5f, 0.5f);
        const ull nhalf2 = pack2(-0.5f, -0.5f);
        const ull one2   = pack2(1.f, 1.f);
        const ull negc2  = pack2(-0.12996509f, -0.12996509f);
        ull acc = pack2(0.f, 0.f);

        int i = rs + tid;
        for (; i + 7*BT < re; i += 8*BT) {
            float4 r[8];
            #pragma unroll
            for (int k = 0; k < 8; k++) r[k] = __ldcs(&hm4[i + k*BT]);
            #pragma unroll
            for (int k = 0; k < 8; k++) {
                floss0_pair(r[k].x, r[k].y, half2, nhalf2, one2, negc2, acc);
                floss0_pair(r[k].z, r[k].w, half2, nhalf2, one2, negc2, acc);
            }
        }
        for (; i < re; i += BT) {
            const float4 a = __ldcs(&hm4[i]);
            floss0_pair(a.x, a.y, half2, nhalf2, one2, negc2, acc);
            floss0_pair(a.z, a.w, half2, nhalf2, one2, negc2, acc);
        }
        float a0, a1;
        unpack2(acc, a0, a1);
        fs = a0 + a1;
    }
    fs += corr;   // block 0 folds its focal corrections into its partial
    (void)floss0s;

    // ======================= block reduction of 6 partials =======================
    float v0 = fs, v1 = ceN, v2 = ceD, v3 = myBox, v4 = myBb, v5 = myGi;
    #pragma unroll
    for (int o = 16; o; o >>= 1) {
        v0 += __shfl_xor_sync(0xffffffffu, v0, o);
        v1 += __shfl_xor_sync(0xffffffffu, v1, o);
        v2 += __shfl_xor_sync(0xffffffffu, v2, o);
        v3 += __shfl_xor_sync(0xffffffffu, v3, o);
        v4 += __shfl_xor_sync(0xffffffffu, v4, o);
        v5 += __shfl_xor_sync(0xffffffffu, v5, o);
    }
    if (lane == 0) {
        redf[wrp][0]=v0; redf[wrp][1]=v1; redf[wrp][2]=v2;
        redf[wrp][3]=v3; redf[wrp][4]=v4; redf[wrp][5]=v5;
    }
    __syncthreads();
    if (wrp == 0) {
        v0 = (lane < NW) ? redf[lane][0] : 0.f;
        v1 = (lane < NW) ? redf[lane][1] : 0.f;
        v2 = (lane < NW) ? redf[lane][2] : 0.f;
        v3 = (lane < NW) ? redf[lane][3] : 0.f;
        v4 = (lane < NW) ? redf[lane][4] : 0.f;
        v5 = (lane < NW) ? redf[lane][5] : 0.f;
        #pragma unroll
        for (int o = 16; o; o >>= 1) {
            v0 += __shfl_xor_sync(0xffffffffu, v0, o);
            v1 += __shfl_xor_sync(0xffffffffu, v1, o);
            v2 += __shfl_xor_sync(0xffffffffu, v2, o);
            v3 += __shfl_xor_sync(0xffffffffu, v3, o);
            v4 += __shfl_xor_sync(0xffffffffu, v4, o);
            v5 += __shfl_xor_sync(0xffffffffu, v5, o);
        }
        if (lane == 0) {
            p_hm[bid] = (double)v0;
            p_cn[bid] = (double)v1;
            p_cd[bid] = (double)v2;
            if (bid == 0) { p_box = (double)v3; p_bb = (double)v4; p_gi = (double)v5; }
        }
    }

    // ======================= last-block finalize =======================
    __threadfence();
    if (tid == 0) isLast = (atomicInc(&g_arrive, G - 1) == G - 1);  // wraps to 0
    __syncthreads();
    if (isLast) {
        __threadfence();
        double a = 0.0, b2 = 0.0, c2 = 0.0;
        for (int i = tid; i < G; i += BT) {
            a  += ((volatile double*)p_hm)[i];
            b2 += ((volatile double*)p_cn)[i];
            c2 += ((volatile double*)p_cd)[i];
        }
        #pragma unroll
        for (int o = 16; o; o >>= 1) {
            a  += __shfl_xor_sync(0xffffffffu, a,  o);
            b2 += __shfl_xor_sync(0xffffffffu, b2, o);
            c2 += __shfl_xor_sync(0xffffffffu, c2, o);
        }
        if (lane == 0) { redd[wrp][0] = a; redd[wrp][1] = b2; redd[wrp][2] = c2; }
        __syncthreads();
        if (wrp == 0) {
            a  = (lane < NW) ? redd[lane][0] : 0.0;
            b2 = (lane < NW) ? redd[lane][1] : 0.0;
            c2 = (lane < NW) ? redd[lane][2] : 0.0;
            #pragma unroll
            for (int o = 16; o; o >>= 1) {
                a  += __shfl_xor_sync(0xffffffffu, a,  o);
                b2 += __shfl_xor_sync(0xffffffffu, b2, o);
                c2 += __shfl_xor_sync(0xffffffffu, c2, o);
            }
            if (lane == 0) {
                const double boxc = *((volatile double*)&p_box);
                const double bb   = *((volatile double*)&p_bb);
                const double gi   = *((volatile double*)&p_gi);
                const int    npI  = *((volatile int*)&p_np);
                const double np   = fmax((double)npI, 1.0);
                const float ce   = (float)(b2 / c2);
                const float bbox = (float)(bb / (double)NJ);
                const float giou = (float)(gi / (double)NJ);
                const float hmv  = (float)(a / np);
                const float bl   = (float)(boxc / np);
                const float aux  = hmv + 5.f * bl;
                out[0] = ce;
                out[1] = bbox;
                out[2] = giou;
                out[3] = aux;
                out[4] = ce + 5.f * bbox + 2.f * giou + aux;
            }
        }
    }
}

extern "C" void kernel_launch(void* const* d_in, const int* in_sizes, int n_in,
                              void* d_out, int out_size)
{
    const float* pred_logits  = (const float*)d_in[0];
    const float* pred_boxes   = (const float*)d_in[1];
    const float* heatmap      = (const float*)d_in[2];
    const float* box_map      = (const float*)d_in[3];
    const float* tgt_boxes    = (const float*)d_in[4];
    const int*   tgt_labels   = (const int*)  d_in[5];
    const float* tgt_sizes    = (const float*)d_in[6];
    const int*   src_idx      = (const int*)  d_in[7];
    const int*   tgt_idx      = (const int*)  d_in[8];
    const float* empty_weight = (const float*)d_in[9];

    k_all<<<G, BT>>>(pred_logits, pred_boxes,
                     (const float4*)heatmap, heatmap, box_map, tgt_boxes,
                     tgt_labels, tgt_sizes, src_idx, tgt_idx, empty_weight,
                     (float*)d_out);
}